// round 1
// baseline (speedup 1.0000x reference)
#include <cuda_runtime.h>
#include <cstdint>
#include <cstddef>

#define N_TOK 4096
#define DM    512
#define NH    8
#define HD    64
#define QK_SCALE 0.125f
#define NUM_GRAPHS 32

// ---------------- scratch (device globals: no allocations allowed) ----------
__device__ float g_q[N_TOK * DM];
__device__ float g_k[N_TOK * DM];
__device__ float g_v[N_TOK * DM];
__device__ float g_attn[N_TOK * DM];
__device__ int   g_gstart[NUM_GRAPHS];
__device__ int   g_gend[NUM_GRAPHS];

// ---------------- tf32 helpers ----------------------------------------------
__device__ __forceinline__ unsigned f2tf(float x) {
    unsigned r;
    asm("cvt.rna.tf32.f32 %0, %1;" : "=r"(r) : "f"(x));
    return r;
}
__device__ __forceinline__ void split3(float x, unsigned &hi, unsigned &lo) {
    hi = f2tf(x);
    lo = f2tf(x - __uint_as_float(hi));
}
__device__ __forceinline__ void mma_tf32(float c[4], const unsigned a[4], const unsigned b[2]) {
    asm volatile(
        "mma.sync.aligned.m16n8k8.row.col.f32.tf32.tf32.f32 "
        "{%0,%1,%2,%3}, {%4,%5,%6,%7}, {%8,%9}, {%0,%1,%2,%3};\n"
        : "+f"(c[0]), "+f"(c[1]), "+f"(c[2]), "+f"(c[3])
        : "r"(a[0]), "r"(a[1]), "r"(a[2]), "r"(a[3]), "r"(b[0]), "r"(b[1]));
}

// ---------------- graph boundary kernel --------------------------------------
__global__ void bounds_kernel(const int* __restrict__ batch) {
    int i = blockIdx.x * blockDim.x + threadIdx.x;
    if (i >= N_TOK) return;
    int b = batch[i];
    if (i == 0 || batch[i - 1] != b) g_gstart[b] = i;
    if (i == N_TOK - 1 || batch[i + 1] != b) g_gend[b] = i + 1;
}

// ---------------- 3xTF32 GEMM: C[m0:+128, n0:+64] = A @ W^T + bias ----------
// A: [4096,512] row-major, W: [Nout,512] row-major, K = 512.
// 256 threads, warp grid 4(m) x 2(n), warp tile 32x32.
__device__ __forceinline__ void gemm3x_body(const float* __restrict__ A,
                                            const float* __restrict__ W,
                                            const float* __restrict__ bias,
                                            float* __restrict__ C,
                                            int m0, int n0) {
    __shared__ float As[128 * 36];
    __shared__ float Ws[64 * 36];
    const int tid  = threadIdx.x;
    const int lane = tid & 31, warp = tid >> 5;
    const int wm = (warp & 3) * 32, wn = (warp >> 2) * 32;
    const int g = lane >> 2, t4 = lane & 3;

    float c[2][4][4];
#pragma unroll
    for (int mi = 0; mi < 2; mi++)
#pragma unroll
        for (int ni = 0; ni < 4; ni++)
#pragma unroll
            for (int j = 0; j < 4; j++) c[mi][ni][j] = 0.f;

    for (int k0 = 0; k0 < 512; k0 += 32) {
#pragma unroll
        for (int i = 0; i < 4; i++) {
            int idx = tid + i * 256;                   // 1024 float4 of A tile
            int r = idx >> 3, c4 = (idx & 7) * 4;
            float4 v = *(const float4*)(&A[(size_t)(m0 + r) * 512 + k0 + c4]);
            float* d = &As[r * 36 + c4];
            d[0] = v.x; d[1] = v.y; d[2] = v.z; d[3] = v.w;
        }
#pragma unroll
        for (int i = 0; i < 2; i++) {
            int idx = tid + i * 256;                   // 512 float4 of W tile
            int r = idx >> 3, c4 = (idx & 7) * 4;
            float4 v = *(const float4*)(&W[(size_t)(n0 + r) * 512 + k0 + c4]);
            float* d = &Ws[r * 36 + c4];
            d[0] = v.x; d[1] = v.y; d[2] = v.z; d[3] = v.w;
        }
        __syncthreads();
#pragma unroll
        for (int kk = 0; kk < 32; kk += 8) {
            unsigned ahi[2][4], alo[2][4], bh[4][2], bl[4][2];
#pragma unroll
            for (int mi = 0; mi < 2; mi++) {
                int rb = wm + mi * 16;
                split3(As[(rb + g) * 36 + kk + t4],         ahi[mi][0], alo[mi][0]);
                split3(As[(rb + g + 8) * 36 + kk + t4],     ahi[mi][1], alo[mi][1]);
                split3(As[(rb + g) * 36 + kk + t4 + 4],     ahi[mi][2], alo[mi][2]);
                split3(As[(rb + g + 8) * 36 + kk + t4 + 4], ahi[mi][3], alo[mi][3]);
            }
#pragma unroll
            for (int ni = 0; ni < 4; ni++) {
                int nb = wn + ni * 8 + g;
                split3(Ws[nb * 36 + kk + t4],     bh[ni][0], bl[ni][0]);
                split3(Ws[nb * 36 + kk + t4 + 4], bh[ni][1], bl[ni][1]);
            }
#pragma unroll
            for (int mi = 0; mi < 2; mi++)
#pragma unroll
                for (int ni = 0; ni < 4; ni++) {
                    mma_tf32(c[mi][ni], alo[mi], bh[ni]);
                    mma_tf32(c[mi][ni], ahi[mi], bl[ni]);
                    mma_tf32(c[mi][ni], ahi[mi], bh[ni]);
                }
        }
        __syncthreads();
    }
#pragma unroll
    for (int mi = 0; mi < 2; mi++)
#pragma unroll
        for (int ni = 0; ni < 4; ni++) {
            int row = m0 + wm + mi * 16 + g;
            int col = n0 + wn + ni * 8 + 2 * t4;
            float2 bb = *(const float2*)(&bias[col]);
            float2 o0 = make_float2(c[mi][ni][0] + bb.x, c[mi][ni][1] + bb.y);
            float2 o1 = make_float2(c[mi][ni][2] + bb.x, c[mi][ni][3] + bb.y);
            *(float2*)(&C[(size_t)row * 512 + col])       = o0;
            *(float2*)(&C[(size_t)(row + 8) * 512 + col]) = o1;
        }
}

__global__ void __launch_bounds__(256) qkv_kernel(const float* __restrict__ x,
                                                  const float* __restrict__ Wq, const float* __restrict__ bq,
                                                  const float* __restrict__ Wk, const float* __restrict__ bk,
                                                  const float* __restrict__ Wv, const float* __restrict__ bv) {
    int seg = blockIdx.y >> 3;                 // 0:q 1:k 2:v
    int n0  = (blockIdx.y & 7) * 64;
    int m0  = blockIdx.x * 128;
    const float* W = (seg == 0) ? Wq : (seg == 1) ? Wk : Wv;
    const float* b = (seg == 0) ? bq : (seg == 1) ? bk : bv;
    float* C       = (seg == 0) ? g_q : (seg == 1) ? g_k : g_v;
    gemm3x_body(x, W, b, C, m0, n0);
}

__global__ void __launch_bounds__(256) out_kernel(const float* __restrict__ Wo,
                                                  const float* __restrict__ bo,
                                                  float* __restrict__ out) {
    gemm3x_body(g_attn, Wo, bo, out, blockIdx.x * 128, blockIdx.y * 64);
}

// ---------------- flash attention with block-diagonal skip -------------------
// grid (64 qtiles, 8 heads), 128 threads (4 warps), warp handles 16 query rows.
#define ASM_STRIDE 68
#define ATT_SMEM ((4 * 64 * ASM_STRIDE) * 4 + 64 * 4)

__global__ void __launch_bounds__(128) attn_kernel(const float* __restrict__ bias,
                                                   const int* __restrict__ batch) {
    extern __shared__ float sm[];
    float* Qs = sm;
    float* Ks = sm + 64 * ASM_STRIDE;
    float* Vs = sm + 2 * 64 * ASM_STRIDE;
    float* Ps = sm + 3 * 64 * ASM_STRIDE;
    int*   kb = (int*)(sm + 4 * 64 * ASM_STRIDE);

    const int h  = blockIdx.y;
    const int q0 = blockIdx.x * 64;
    const int tid = threadIdx.x;
    const int lane = tid & 31, warp = tid >> 5;
    const int g = lane >> 2, t4 = lane & 3;
    const int r0 = warp * 16 + g, r1 = r0 + 8;

    // load Q tile (64 x 64)
#pragma unroll
    for (int i = 0; i < 8; i++) {
        int idx = tid + i * 128;
        int r = idx >> 4, c4 = (idx & 15) * 4;
        float4 v = *(const float4*)(&g_q[(size_t)(q0 + r) * DM + h * HD + c4]);
        float* d = &Qs[r * ASM_STRIDE + c4];
        d[0] = v.x; d[1] = v.y; d[2] = v.z; d[3] = v.w;
    }

    const int qb0 = batch[q0 + r0];
    const int qb1 = batch[q0 + r1];
    const int kbeg = g_gstart[batch[q0]];
    const int kend = g_gend[batch[q0 + 63]];
    const int t0 = kbeg >> 6, t1 = (kend + 63) >> 6;

    float m0 = -1e30f, m1 = -1e30f, l0 = 0.f, l1 = 0.f;
    float O[8][4];
#pragma unroll
    for (int ni = 0; ni < 8; ni++) { O[ni][0] = O[ni][1] = O[ni][2] = O[ni][3] = 0.f; }

    for (int kt = t0; kt < t1; kt++) {
        const int kbase = kt * 64;
        __syncthreads();
#pragma unroll
        for (int i = 0; i < 8; i++) {
            int idx = tid + i * 128;
            int r = idx >> 4, c4 = (idx & 15) * 4;
            float4 kv = *(const float4*)(&g_k[(size_t)(kbase + r) * DM + h * HD + c4]);
            float* dk = &Ks[r * ASM_STRIDE + c4];
            dk[0] = kv.x; dk[1] = kv.y; dk[2] = kv.z; dk[3] = kv.w;
            float4 vv = *(const float4*)(&g_v[(size_t)(kbase + r) * DM + h * HD + c4]);
            float* dv = &Vs[r * ASM_STRIDE + c4];
            dv[0] = vv.x; dv[1] = vv.y; dv[2] = vv.z; dv[3] = vv.w;
        }
        if (tid < 64) kb[tid] = batch[kbase + tid];
        __syncthreads();

        // S = Q @ K^T (3xTF32)
        float s[8][4];
#pragma unroll
        for (int ni = 0; ni < 8; ni++) { s[ni][0] = s[ni][1] = s[ni][2] = s[ni][3] = 0.f; }
#pragma unroll
        for (int kk = 0; kk < 64; kk += 8) {
            unsigned ahi[4], alo[4];
            split3(Qs[r0 * ASM_STRIDE + kk + t4],     ahi[0], alo[0]);
            split3(Qs[r1 * ASM_STRIDE + kk + t4],     ahi[1], alo[1]);
            split3(Qs[r0 * ASM_STRIDE + kk + t4 + 4], ahi[2], alo[2]);
            split3(Qs[r1 * ASM_STRIDE + kk + t4 + 4], ahi[3], alo[3]);
#pragma unroll
            for (int ni = 0; ni < 8; ni++) {
                unsigned bh[2], bl[2];
                split3(Ks[(ni * 8 + g) * ASM_STRIDE + kk + t4],     bh[0], bl[0]);
                split3(Ks[(ni * 8 + g) * ASM_STRIDE + kk + t4 + 4], bh[1], bl[1]);
                mma_tf32(s[ni], alo, bh);
                mma_tf32(s[ni], ahi, bl);
                mma_tf32(s[ni], ahi, bh);
            }
        }

        // scale + bias + mask (in place)
        const float* bp = bias + (size_t)h * N_TOK * N_TOK;
        float pm0 = -1e30f, pm1 = -1e30f;
#pragma unroll
        for (int ni = 0; ni < 8; ni++) {
            int cc = ni * 8 + 2 * t4;
            int c0 = kbase + cc;
            float2 b0 = *(const float2*)(bp + (size_t)(q0 + r0) * N_TOK + c0);
            float2 b1 = *(const float2*)(bp + (size_t)(q0 + r1) * N_TOK + c0);
            int k0 = kb[cc], k1 = kb[cc + 1];
            s[ni][0] = (k0 == qb0) ? fmaf(s[ni][0], QK_SCALE, b0.x) : -1e30f;
            s[ni][1] = (k1 == qb0) ? fmaf(s[ni][1], QK_SCALE, b0.y) : -1e30f;
            s[ni][2] = (k0 == qb1) ? fmaf(s[ni][2], QK_SCALE, b1.x) : -1e30f;
            s[ni][3] = (k1 == qb1) ? fmaf(s[ni][3], QK_SCALE, b1.y) : -1e30f;
            pm0 = fmaxf(pm0, fmaxf(s[ni][0], s[ni][1]));
            pm1 = fmaxf(pm1, fmaxf(s[ni][2], s[ni][3]));
        }
        pm0 = fmaxf(pm0, __shfl_xor_sync(0xffffffffu, pm0, 1));
        pm0 = fmaxf(pm0, __shfl_xor_sync(0xffffffffu, pm0, 2));
        pm1 = fmaxf(pm1, __shfl_xor_sync(0xffffffffu, pm1, 1));
        pm1 = fmaxf(pm1, __shfl_xor_sync(0xffffffffu, pm1, 2));

        float nm0 = fmaxf(m0, pm0), nm1 = fmaxf(m1, pm1);
        float al0 = __expf(m0 - nm0), al1 = __expf(m1 - nm1);
        m0 = nm0; m1 = nm1;

        float rs0 = 0.f, rs1 = 0.f;
#pragma unroll
        for (int ni = 0; ni < 8; ni++) {
            int cc = ni * 8 + 2 * t4;
            float p00 = __expf(s[ni][0] - nm0);
            float p01 = __expf(s[ni][1] - nm0);
            float p10 = __expf(s[ni][2] - nm1);
            float p11 = __expf(s[ni][3] - nm1);
            rs0 += p00 + p01;
            rs1 += p10 + p11;
            Ps[r0 * ASM_STRIDE + cc]     = p00;
            Ps[r0 * ASM_STRIDE + cc + 1] = p01;
            Ps[r1 * ASM_STRIDE + cc]     = p10;
            Ps[r1 * ASM_STRIDE + cc + 1] = p11;
        }
        rs0 += __shfl_xor_sync(0xffffffffu, rs0, 1);
        rs0 += __shfl_xor_sync(0xffffffffu, rs0, 2);
        rs1 += __shfl_xor_sync(0xffffffffu, rs1, 1);
        rs1 += __shfl_xor_sync(0xffffffffu, rs1, 2);
        l0 = l0 * al0 + rs0;
        l1 = l1 * al1 + rs1;
#pragma unroll
        for (int ni = 0; ni < 8; ni++) {
            O[ni][0] *= al0; O[ni][1] *= al0;
            O[ni][2] *= al1; O[ni][3] *= al1;
        }
        __syncwarp();

        // O += P @ V (single tf32)
#pragma unroll
        for (int kk = 0; kk < 64; kk += 8) {
            unsigned pa[4];
            pa[0] = f2tf(Ps[r0 * ASM_STRIDE + kk + t4]);
            pa[1] = f2tf(Ps[r1 * ASM_STRIDE + kk + t4]);
            pa[2] = f2tf(Ps[r0 * ASM_STRIDE + kk + t4 + 4]);
            pa[3] = f2tf(Ps[r1 * ASM_STRIDE + kk + t4 + 4]);
#pragma unroll
            for (int ni = 0; ni < 8; ni++) {
                unsigned vb[2];
                vb[0] = f2tf(Vs[(kk + t4) * ASM_STRIDE + ni * 8 + g]);
                vb[1] = f2tf(Vs[(kk + t4 + 4) * ASM_STRIDE + ni * 8 + g]);
                mma_tf32(O[ni], pa, vb);
            }
        }
        __syncwarp();
    }

    float inv0 = 1.f / l0, inv1 = 1.f / l1;
#pragma unroll
    for (int ni = 0; ni < 8; ni++) {
        int col = h * HD + ni * 8 + 2 * t4;
        float2 o0 = make_float2(O[ni][0] * inv0, O[ni][1] * inv0);
        float2 o1 = make_float2(O[ni][2] * inv1, O[ni][3] * inv1);
        *(float2*)(&g_attn[(size_t)(q0 + r0) * DM + col]) = o0;
        *(float2*)(&g_attn[(size_t)(q0 + r1) * DM + col]) = o1;
    }
}

// ---------------- launch -----------------------------------------------------
extern "C" void kernel_launch(void* const* d_in, const int* in_sizes, int n_in,
                              void* d_out, int out_size) {
    const float* x    = (const float*)d_in[0];
    const float* bias = (const float*)d_in[1];
    const int*   batch = (const int*)d_in[2];
    const float* Wq = (const float*)d_in[3];
    const float* bq = (const float*)d_in[4];
    const float* Wk = (const float*)d_in[5];
    const float* bk = (const float*)d_in[6];
    const float* Wv = (const float*)d_in[7];
    const float* bv = (const float*)d_in[8];
    const float* Wo = (const float*)d_in[9];
    const float* bo = (const float*)d_in[10];
    float* out = (float*)d_out;

    bounds_kernel<<<16, 256>>>(batch);
    qkv_kernel<<<dim3(32, 24), 256>>>(x, Wq, bq, Wk, bk, Wv, bv);

    cudaFuncSetAttribute((const void*)attn_kernel,
                         cudaFuncAttributeMaxDynamicSharedMemorySize, ATT_SMEM);
    attn_kernel<<<dim3(64, 8), 128, ATT_SMEM>>>(bias, batch);

    out_kernel<<<dim3(32, 8), 256>>>(Wo, bo, out);
}

// round 3
// speedup vs baseline: 1.4773x; 1.4773x over previous
#include <cuda_runtime.h>
#include <cuda_bf16.h>
#include <cstdint>
#include <cstddef>

#define N_TOK 4096
#define DM    512
#define NH    8
#define HD    64
#define QK_SCALE 0.125f
#define NUM_GRAPHS 32

// ---------------- scratch (device globals: no allocations allowed) ----------
__device__ float g_q[N_TOK * DM];
__device__ float g_k[N_TOK * DM];
__device__ float g_v[N_TOK * DM];
__device__ int   g_gstart[NUM_GRAPHS];
__device__ int   g_gend[NUM_GRAPHS];

// bf16 hi/lo planes for GEMM inputs
__device__ __nv_bfloat16 g_xh[N_TOK * DM], g_xl[N_TOK * DM];
__device__ __nv_bfloat16 g_wh[4][DM * DM], g_wl[4][DM * DM];
__device__ __nv_bfloat16 g_oh[N_TOK * DM], g_ol[N_TOK * DM];

// ---------------- helpers ----------------------------------------------------
__device__ __forceinline__ unsigned f2tf(float x) {
    unsigned r;
    asm("cvt.rna.tf32.f32 %0, %1;" : "=r"(r) : "f"(x));
    return r;
}
__device__ __forceinline__ void split3(float x, unsigned &hi, unsigned &lo) {
    hi = f2tf(x);
    lo = f2tf(x - __uint_as_float(hi));
}
__device__ __forceinline__ void mma_tf32(float c[4], const unsigned a[4], const unsigned b[2]) {
    asm volatile(
        "mma.sync.aligned.m16n8k8.row.col.f32.tf32.tf32.f32 "
        "{%0,%1,%2,%3}, {%4,%5,%6,%7}, {%8,%9}, {%0,%1,%2,%3};\n"
        : "+f"(c[0]), "+f"(c[1]), "+f"(c[2]), "+f"(c[3])
        : "r"(a[0]), "r"(a[1]), "r"(a[2]), "r"(a[3]), "r"(b[0]), "r"(b[1]));
}
__device__ __forceinline__ void mma_bf16(float c[4], const unsigned a[4], const unsigned b[2]) {
    asm volatile(
        "mma.sync.aligned.m16n8k16.row.col.f32.bf16.bf16.f32 "
        "{%0,%1,%2,%3}, {%4,%5,%6,%7}, {%8,%9}, {%0,%1,%2,%3};\n"
        : "+f"(c[0]), "+f"(c[1]), "+f"(c[2]), "+f"(c[3])
        : "r"(a[0]), "r"(a[1]), "r"(a[2]), "r"(a[3]), "r"(b[0]), "r"(b[1]));
}
__device__ __forceinline__ unsigned smem_u32(const void* p) {
    return (unsigned)__cvta_generic_to_shared(p);
}
__device__ __forceinline__ void cp16(void* dst, const void* src) {
    asm volatile("cp.async.cg.shared.global [%0], [%1], 16;\n"
                 :: "r"(smem_u32(dst)), "l"(src));
}
__device__ __forceinline__ void cp_commit() {
    asm volatile("cp.async.commit_group;\n");
}

// ---------------- graph boundary kernel --------------------------------------
__global__ void bounds_kernel(const int* __restrict__ batch) {
    int i = blockIdx.x * blockDim.x + threadIdx.x;
    if (i >= N_TOK) return;
    int b = batch[i];
    if (i == 0 || batch[i - 1] != b) g_gstart[b] = i;
    if (i == N_TOK - 1 || batch[i + 1] != b) g_gend[b] = i + 1;
}

// ---------------- prep: split fp32 -> bf16 hi/lo planes ----------------------
__global__ void __launch_bounds__(256) prep_kernel(const float* __restrict__ x,
                                                   const float* __restrict__ Wq,
                                                   const float* __restrict__ Wk,
                                                   const float* __restrict__ Wv,
                                                   const float* __restrict__ Wo) {
    size_t base = ((size_t)blockIdx.x * 256 + threadIdx.x) * 4;
    const float* src;
    __nv_bfloat16 *dh, *dl;
    size_t off;
    if (base < (size_t)N_TOK * DM) {
        src = x; dh = g_xh; dl = g_xl; off = base;
    } else {
        size_t r = base - (size_t)N_TOK * DM;
        int mat = (int)(r >> 18);
        off = r & ((1u << 18) - 1);
        src = (mat == 0) ? Wq : (mat == 1) ? Wk : (mat == 2) ? Wv : Wo;
        dh = g_wh[mat]; dl = g_wl[mat];
    }
    float4 v = *(const float4*)(src + off);
    float f[4] = {v.x, v.y, v.z, v.w};
    __nv_bfloat16 h[4], l[4];
#pragma unroll
    for (int i = 0; i < 4; i++) {
        h[i] = __float2bfloat16_rn(f[i]);
        l[i] = __float2bfloat16_rn(f[i] - __bfloat162float(h[i]));
    }
    __nv_bfloat162 h0; h0.x = h[0]; h0.y = h[1];
    __nv_bfloat162 h1; h1.x = h[2]; h1.y = h[3];
    __nv_bfloat162 l0; l0.x = l[0]; l0.y = l[1];
    __nv_bfloat162 l1; l1.x = l[2]; l1.y = l[3];
    *(__nv_bfloat162*)(dh + off)     = h0;
    *(__nv_bfloat162*)(dh + off + 2) = h1;
    *(__nv_bfloat162*)(dl + off)     = l0;
    *(__nv_bfloat162*)(dl + off + 2) = l1;
}

// ---------------- bf16x3 pipelined GEMM --------------------------------------
// C[m0:+128, n0:+128] = A @ B^T + bias.  A,B given as bf16 hi/lo planes with
// leading dim 512.  256 threads, warp grid 4(m) x 2(n), warp tile 32x64.
#define KT   32
#define RS   40                    // smem row stride in bf16 (80B, 16B aligned)
#define PLANE (128 * RS)           // bf16 elems per plane per stage
#define STAGE_ELEMS (4 * PLANE)    // Ah, Al, Bh, Bl
#define GEMM_SMEM (2 * STAGE_ELEMS * 2)   // bytes (2 stages, 2B/elem) = 81920

__device__ __forceinline__ void load_stage(__nv_bfloat16* st,
                                           const __nv_bfloat16* Ah, const __nv_bfloat16* Al,
                                           const __nv_bfloat16* Bh, const __nv_bfloat16* Bl,
                                           int m0, int n0, int k0, int tid) {
#pragma unroll
    for (int i = 0; i < 2; i++) {
        int cidx = tid + i * 256;          // 512 16B chunks per plane
        int row  = cidx >> 2;
        int part = (cidx & 3) * 8;         // bf16 offset within row
        cp16(st + 0 * PLANE + row * RS + part, Ah + (size_t)(m0 + row) * DM + k0 + part);
        cp16(st + 1 * PLANE + row * RS + part, Al + (size_t)(m0 + row) * DM + k0 + part);
        cp16(st + 2 * PLANE + row * RS + part, Bh + (size_t)(n0 + row) * DM + k0 + part);
        cp16(st + 3 * PLANE + row * RS + part, Bl + (size_t)(n0 + row) * DM + k0 + part);
    }
}

__device__ __forceinline__ void gemm_body(const __nv_bfloat16* __restrict__ Ah,
                                          const __nv_bfloat16* __restrict__ Al,
                                          const __nv_bfloat16* __restrict__ Bh,
                                          const __nv_bfloat16* __restrict__ Bl,
                                          const float* __restrict__ bias,
                                          float* __restrict__ C,
                                          int m0, int n0) {
    extern __shared__ __nv_bfloat16 smem_g[];
    const int tid  = threadIdx.x;
    const int lane = tid & 31, warp = tid >> 5;
    const int wm = (warp & 3) * 32, wn = (warp >> 2) * 64;
    const int g = lane >> 2, t4 = lane & 3;

    float c[2][8][4];
#pragma unroll
    for (int mi = 0; mi < 2; mi++)
#pragma unroll
        for (int ni = 0; ni < 8; ni++)
#pragma unroll
            for (int j = 0; j < 4; j++) c[mi][ni][j] = 0.f;

    load_stage(smem_g, Ah, Al, Bh, Bl, m0, n0, 0, tid);
    cp_commit();

    for (int kt = 0; kt < 16; kt++) {
        if (kt < 15) {
            load_stage(smem_g + ((kt + 1) & 1) * STAGE_ELEMS, Ah, Al, Bh, Bl,
                       m0, n0, (kt + 1) * KT, tid);
            cp_commit();
            asm volatile("cp.async.wait_group 1;\n");
        } else {
            asm volatile("cp.async.wait_group 0;\n");
        }
        __syncthreads();

        const __nv_bfloat16* st  = smem_g + (kt & 1) * STAGE_ELEMS;
        const __nv_bfloat16* sAh = st;
        const __nv_bfloat16* sAl = st + PLANE;
        const __nv_bfloat16* sBh = st + 2 * PLANE;
        const __nv_bfloat16* sBl = st + 3 * PLANE;

#pragma unroll
        for (int kk = 0; kk < KT; kk += 16) {
            unsigned ah[2][4], al[2][4];
#pragma unroll
            for (int mi = 0; mi < 2; mi++) {
                int o0 = (wm + mi * 16 + g) * RS + kk + 2 * t4;
                ah[mi][0] = *(const unsigned*)(sAh + o0);
                ah[mi][1] = *(const unsigned*)(sAh + o0 + 8 * RS);
                ah[mi][2] = *(const unsigned*)(sAh + o0 + 8);
                ah[mi][3] = *(const unsigned*)(sAh + o0 + 8 * RS + 8);
                al[mi][0] = *(const unsigned*)(sAl + o0);
                al[mi][1] = *(const unsigned*)(sAl + o0 + 8 * RS);
                al[mi][2] = *(const unsigned*)(sAl + o0 + 8);
                al[mi][3] = *(const unsigned*)(sAl + o0 + 8 * RS + 8);
            }
#pragma unroll
            for (int ni = 0; ni < 8; ni++) {
                int o = (wn + ni * 8 + g) * RS + kk + 2 * t4;
                unsigned bh[2], bl[2];
                bh[0] = *(const unsigned*)(sBh + o);
                bh[1] = *(const unsigned*)(sBh + o + 8);
                bl[0] = *(const unsigned*)(sBl + o);
                bl[1] = *(const unsigned*)(sBl + o + 8);
#pragma unroll
                for (int mi = 0; mi < 2; mi++) {
                    mma_bf16(c[mi][ni], al[mi], bh);
                    mma_bf16(c[mi][ni], ah[mi], bl);
                    mma_bf16(c[mi][ni], ah[mi], bh);
                }
            }
        }
        __syncthreads();
    }

#pragma unroll
    for (int mi = 0; mi < 2; mi++)
#pragma unroll
        for (int ni = 0; ni < 8; ni++) {
            int row = m0 + wm + mi * 16 + g;
            int col = n0 + wn + ni * 8 + 2 * t4;
            float2 bb = *(const float2*)(&bias[col]);
            float2 o0 = make_float2(c[mi][ni][0] + bb.x, c[mi][ni][1] + bb.y);
            float2 o1 = make_float2(c[mi][ni][2] + bb.x, c[mi][ni][3] + bb.y);
            *(float2*)(&C[(size_t)row * DM + col])       = o0;
            *(float2*)(&C[(size_t)(row + 8) * DM + col]) = o1;
        }
}

__global__ void __launch_bounds__(256, 1) qkv_kernel(const float* __restrict__ bq,
                                                     const float* __restrict__ bk,
                                                     const float* __restrict__ bv) {
    int mat = blockIdx.y >> 2;                 // 0:q 1:k 2:v
    int n0  = (blockIdx.y & 3) * 128;
    int m0  = blockIdx.x * 128;
    const float* b = (mat == 0) ? bq : (mat == 1) ? bk : bv;
    float* C       = (mat == 0) ? g_q : (mat == 1) ? g_k : g_v;
    gemm_body(g_xh, g_xl, g_wh[mat], g_wl[mat], b, C, m0, n0);
}

__global__ void __launch_bounds__(256, 1) out_kernel(const float* __restrict__ bo,
                                                     float* __restrict__ out) {
    gemm_body(g_oh, g_ol, g_wh[3], g_wl[3], bo, out,
              blockIdx.x * 128, blockIdx.y * 128);
}

// ---------------- flash attention with block-diagonal skip -------------------
// grid (64 qtiles, 8 heads), 128 threads (4 warps), warp handles 16 query rows.
#define ASM_STRIDE 68
#define ATT_SMEM ((4 * 64 * ASM_STRIDE) * 4 + 64 * 4)

__global__ void __launch_bounds__(128) attn_kernel(const float* __restrict__ bias,
                                                   const int* __restrict__ batch) {
    extern __shared__ float sm[];
    float* Qs = sm;
    float* Ks = sm + 64 * ASM_STRIDE;
    float* Vs = sm + 2 * 64 * ASM_STRIDE;
    float* Ps = sm + 3 * 64 * ASM_STRIDE;
    int*   kb = (int*)(sm + 4 * 64 * ASM_STRIDE);

    const int h  = blockIdx.y;
    const int q0 = blockIdx.x * 64;
    const int tid = threadIdx.x;
    const int lane = tid & 31, warp = tid >> 5;
    const int g = lane >> 2, t4 = lane & 3;
    const int r0 = warp * 16 + g, r1 = r0 + 8;

    // load Q tile (64 x 64)
#pragma unroll
    for (int i = 0; i < 8; i++) {
        int idx = tid + i * 128;
        int r = idx >> 4, c4 = (idx & 15) * 4;
        float4 v = *(const float4*)(&g_q[(size_t)(q0 + r) * DM + h * HD + c4]);
        float* d = &Qs[r * ASM_STRIDE + c4];
        d[0] = v.x; d[1] = v.y; d[2] = v.z; d[3] = v.w;
    }

    const int qb0 = batch[q0 + r0];
    const int qb1 = batch[q0 + r1];
    const int kbeg = g_gstart[batch[q0]];
    const int kend = g_gend[batch[q0 + 63]];
    const int t0 = kbeg >> 6, t1 = (kend + 63) >> 6;

    float m0 = -1e30f, m1 = -1e30f, l0 = 0.f, l1 = 0.f;
    float O[8][4];
#pragma unroll
    for (int ni = 0; ni < 8; ni++) { O[ni][0] = O[ni][1] = O[ni][2] = O[ni][3] = 0.f; }

    for (int kt = t0; kt < t1; kt++) {
        const int kbase = kt * 64;
        __syncthreads();
#pragma unroll
        for (int i = 0; i < 8; i++) {
            int idx = tid + i * 128;
            int r = idx >> 4, c4 = (idx & 15) * 4;
            float4 kv = *(const float4*)(&g_k[(size_t)(kbase + r) * DM + h * HD + c4]);
            float* dk = &Ks[r * ASM_STRIDE + c4];
            dk[0] = kv.x; dk[1] = kv.y; dk[2] = kv.z; dk[3] = kv.w;
            float4 vv = *(const float4*)(&g_v[(size_t)(kbase + r) * DM + h * HD + c4]);
            float* dv = &Vs[r * ASM_STRIDE + c4];
            dv[0] = vv.x; dv[1] = vv.y; dv[2] = vv.z; dv[3] = vv.w;
        }
        if (tid < 64) kb[tid] = batch[kbase + tid];
        __syncthreads();

        // S = Q @ K^T (3xTF32)
        float s[8][4];
#pragma unroll
        for (int ni = 0; ni < 8; ni++) { s[ni][0] = s[ni][1] = s[ni][2] = s[ni][3] = 0.f; }
#pragma unroll
        for (int kk = 0; kk < 64; kk += 8) {
            unsigned ahi[4], alo[4];
            split3(Qs[r0 * ASM_STRIDE + kk + t4],     ahi[0], alo[0]);
            split3(Qs[r1 * ASM_STRIDE + kk + t4],     ahi[1], alo[1]);
            split3(Qs[r0 * ASM_STRIDE + kk + t4 + 4], ahi[2], alo[2]);
            split3(Qs[r1 * ASM_STRIDE + kk + t4 + 4], ahi[3], alo[3]);
#pragma unroll
            for (int ni = 0; ni < 8; ni++) {
                unsigned bh[2], bl[2];
                split3(Ks[(ni * 8 + g) * ASM_STRIDE + kk + t4],     bh[0], bl[0]);
                split3(Ks[(ni * 8 + g) * ASM_STRIDE + kk + t4 + 4], bh[1], bl[1]);
                mma_tf32(s[ni], alo, bh);
                mma_tf32(s[ni], ahi, bl);
                mma_tf32(s[ni], ahi, bh);
            }
        }

        // scale + bias + mask (in place)
        const float* bp = bias + (size_t)h * N_TOK * N_TOK;
        float pm0 = -1e30f, pm1 = -1e30f;
#pragma unroll
        for (int ni = 0; ni < 8; ni++) {
            int cc = ni * 8 + 2 * t4;
            int c0 = kbase + cc;
            float2 b0 = *(const float2*)(bp + (size_t)(q0 + r0) * N_TOK + c0);
            float2 b1 = *(const float2*)(bp + (size_t)(q0 + r1) * N_TOK + c0);
            int k0 = kb[cc], k1 = kb[cc + 1];
            s[ni][0] = (k0 == qb0) ? fmaf(s[ni][0], QK_SCALE, b0.x) : -1e30f;
            s[ni][1] = (k1 == qb0) ? fmaf(s[ni][1], QK_SCALE, b0.y) : -1e30f;
            s[ni][2] = (k0 == qb1) ? fmaf(s[ni][2], QK_SCALE, b1.x) : -1e30f;
            s[ni][3] = (k1 == qb1) ? fmaf(s[ni][3], QK_SCALE, b1.y) : -1e30f;
            pm0 = fmaxf(pm0, fmaxf(s[ni][0], s[ni][1]));
            pm1 = fmaxf(pm1, fmaxf(s[ni][2], s[ni][3]));
        }
        pm0 = fmaxf(pm0, __shfl_xor_sync(0xffffffffu, pm0, 1));
        pm0 = fmaxf(pm0, __shfl_xor_sync(0xffffffffu, pm0, 2));
        pm1 = fmaxf(pm1, __shfl_xor_sync(0xffffffffu, pm1, 1));
        pm1 = fmaxf(pm1, __shfl_xor_sync(0xffffffffu, pm1, 2));

        float nm0 = fmaxf(m0, pm0), nm1 = fmaxf(m1, pm1);
        float al0 = __expf(m0 - nm0), al1 = __expf(m1 - nm1);
        m0 = nm0; m1 = nm1;

        float rs0 = 0.f, rs1 = 0.f;
#pragma unroll
        for (int ni = 0; ni < 8; ni++) {
            int cc = ni * 8 + 2 * t4;
            float p00 = __expf(s[ni][0] - nm0);
            float p01 = __expf(s[ni][1] - nm0);
            float p10 = __expf(s[ni][2] - nm1);
            float p11 = __expf(s[ni][3] - nm1);
            rs0 += p00 + p01;
            rs1 += p10 + p11;
            Ps[r0 * ASM_STRIDE + cc]     = p00;
            Ps[r0 * ASM_STRIDE + cc + 1] = p01;
            Ps[r1 * ASM_STRIDE + cc]     = p10;
            Ps[r1 * ASM_STRIDE + cc + 1] = p11;
        }
        rs0 += __shfl_xor_sync(0xffffffffu, rs0, 1);
        rs0 += __shfl_xor_sync(0xffffffffu, rs0, 2);
        rs1 += __shfl_xor_sync(0xffffffffu, rs1, 1);
        rs1 += __shfl_xor_sync(0xffffffffu, rs1, 2);
        l0 = l0 * al0 + rs0;
        l1 = l1 * al1 + rs1;
#pragma unroll
        for (int ni = 0; ni < 8; ni++) {
            O[ni][0] *= al0; O[ni][1] *= al0;
            O[ni][2] *= al1; O[ni][3] *= al1;
        }
        __syncwarp();

        // O += P @ V (single tf32)
#pragma unroll
        for (int kk = 0; kk < 64; kk += 8) {
            unsigned pa[4];
            pa[0] = f2tf(Ps[r0 * ASM_STRIDE + kk + t4]);
            pa[1] = f2tf(Ps[r1 * ASM_STRIDE + kk + t4]);
            pa[2] = f2tf(Ps[r0 * ASM_STRIDE + kk + t4 + 4]);
            pa[3] = f2tf(Ps[r1 * ASM_STRIDE + kk + t4 + 4]);
#pragma unroll
            for (int ni = 0; ni < 8; ni++) {
                unsigned vb[2];
                vb[0] = f2tf(Vs[(kk + t4) * ASM_STRIDE + ni * 8 + g]);
                vb[1] = f2tf(Vs[(kk + t4 + 4) * ASM_STRIDE + ni * 8 + g]);
                mma_tf32(O[ni], pa, vb);
            }
        }
        __syncwarp();
    }

    float inv0 = 1.f / l0, inv1 = 1.f / l1;
#pragma unroll
    for (int ni = 0; ni < 8; ni++) {
        int col = h * HD + ni * 8 + 2 * t4;
        float o00 = O[ni][0] * inv0, o01 = O[ni][1] * inv0;
        float o10 = O[ni][2] * inv1, o11 = O[ni][3] * inv1;
        __nv_bfloat162 h0, h1, lo0, lo1;
        h0.x = __float2bfloat16_rn(o00);
        h0.y = __float2bfloat16_rn(o01);
        h1.x = __float2bfloat16_rn(o10);
        h1.y = __float2bfloat16_rn(o11);
        lo0.x = __float2bfloat16_rn(o00 - __bfloat162float(h0.x));
        lo0.y = __float2bfloat16_rn(o01 - __bfloat162float(h0.y));
        lo1.x = __float2bfloat16_rn(o10 - __bfloat162float(h1.x));
        lo1.y = __float2bfloat16_rn(o11 - __bfloat162float(h1.y));
        *(__nv_bfloat162*)(&g_oh[(size_t)(q0 + r0) * DM + col]) = h0;
        *(__nv_bfloat162*)(&g_ol[(size_t)(q0 + r0) * DM + col]) = lo0;
        *(__nv_bfloat162*)(&g_oh[(size_t)(q0 + r1) * DM + col]) = h1;
        *(__nv_bfloat162*)(&g_ol[(size_t)(q0 + r1) * DM + col]) = lo1;
    }
}

// ---------------- launch -----------------------------------------------------
extern "C" void kernel_launch(void* const* d_in, const int* in_sizes, int n_in,
                              void* d_out, int out_size) {
    const float* x    = (const float*)d_in[0];
    const float* bias = (const float*)d_in[1];
    const int*   batch = (const int*)d_in[2];
    const float* Wq = (const float*)d_in[3];
    const float* bq = (const float*)d_in[4];
    const float* Wk = (const float*)d_in[5];
    const float* bk = (const float*)d_in[6];
    const float* Wv = (const float*)d_in[7];
    const float* bv = (const float*)d_in[8];
    const float* Wo = (const float*)d_in[9];
    const float* bo = (const float*)d_in[10];
    float* out = (float*)d_out;

    cudaFuncSetAttribute((const void*)qkv_kernel,
                         cudaFuncAttributeMaxDynamicSharedMemorySize, GEMM_SMEM);
    cudaFuncSetAttribute((const void*)out_kernel,
                         cudaFuncAttributeMaxDynamicSharedMemorySize, GEMM_SMEM);
    cudaFuncSetAttribute((const void*)attn_kernel,
                         cudaFuncAttributeMaxDynamicSharedMemorySize, ATT_SMEM);

    bounds_kernel<<<16, 256>>>(batch);
    prep_kernel<<<3072, 256>>>(x, Wq, Wk, Wv, Wo);
    qkv_kernel<<<dim3(32, 12), 256, GEMM_SMEM>>>(bq, bk, bv);
    attn_kernel<<<dim3(64, 8), 128, ATT_SMEM>>>(bias, batch);
    out_kernel<<<dim3(32, 4), 256, GEMM_SMEM>>>(bo, out);
}